// round 9
// baseline (speedup 1.0000x reference)
#include <cuda_runtime.h>

#define I_DIM 28
#define H_DIM 64
#define T_DIM 128
#define B_DIM 4096
#define OUT_DIM 10
#define TI (T_DIM * I_DIM)          // 3584
#define ROWS 28                     // batch rows per CTA (14 pairs)
#define THREADS 256
#define NBLOCKS 147                 // one CTA per SM
#define ST 18                       // pair-row stride in u64 (144B)
#define ST_F 36

typedef unsigned long long u64;

__device__ __forceinline__ u64 pack2(float lo, float hi) {
    u64 r; asm("mov.b64 %0, {%1, %2};" : "=l"(r) : "f"(lo), "f"(hi)); return r;
}
__device__ __forceinline__ void unpack2(u64 v, float& lo, float& hi) {
    asm("mov.b64 {%0, %1}, %2;" : "=f"(lo), "=f"(hi) : "l"(v));
}
__device__ __forceinline__ u64 ffma2(u64 a, u64 b, u64 c) {
    u64 d; asm("fma.rn.f32x2 %0, %1, %2, %3;" : "=l"(d) : "l"(a), "l"(b), "l"(c)); return d;
}
// ---- PROVEN activations (end-to-end rel_err 2.9e-7; tanh.approx is NOT safe here) ----
__device__ __forceinline__ float rcpa(float x) { float r; asm("rcp.approx.f32 %0, %1;" : "=f"(r) : "f"(x)); return r; }
__device__ __forceinline__ float ex2a(float x) { float r; asm("ex2.approx.f32 %0, %1;" : "=f"(r) : "f"(x)); return r; }
__device__ __forceinline__ float sigm(float x)  { return rcpa(1.0f + ex2a(-1.4426950408889634f * x)); }
__device__ __forceinline__ float tanh_(float x) { return fmaf(2.0f, rcpa(1.0f + ex2a(-2.8853900817779268f * x)), -1.0f); }

// group-local barrier: 64 threads (2 warps) of pair-group q
__device__ __forceinline__ void bar_group(int barid) {
    asm volatile("bar.sync %0, 64;" :: "r"(barid) : "memory");
}

// smem (bytes): sWhh 65536 | sWih 28672 | sb 1024 | shT 2x64x18 u64 = 18432 | sxT 2x28x18 u64 = 8064
#define SMEM_BYTES (65536 + 28672 + 1024 + 18432 + 8064)   // 121728

template<int NR, int NP, int PB>
__device__ __forceinline__ void accum(const float4* __restrict__ Wm,
                                      const u64* __restrict__ vbuf,
                                      int u, u64* a0, u64* a1, u64* a2, u64* a3)
{
    #pragma unroll 4
    for (int r = 0; r < NR; ++r) {
        float4 w = Wm[(r << 6) + u];
        u64 wi = pack2(w.x, w.x), wf = pack2(w.y, w.y);
        u64 wg = pack2(w.z, w.z), wo = pack2(w.w, w.w);
        const u64* vr = vbuf + r * ST;
        u64 v[NP];
        if constexpr (NP == 4) {
            ulonglong2 p0 = *(const ulonglong2*)(vr + PB);
            ulonglong2 p1 = *(const ulonglong2*)(vr + PB + 2);
            v[0] = p0.x; v[1] = p0.y; v[2] = p1.x; v[3] = p1.y;
        } else if constexpr (PB == 8) {
            ulonglong2 p0 = *(const ulonglong2*)(vr + 8);
            v[0] = p0.x; v[1] = p0.y; v[2] = vr[10];
        } else {  // PB == 11
            v[0] = vr[11];
            ulonglong2 p1 = *(const ulonglong2*)(vr + 12);
            v[1] = p1.x; v[2] = p1.y;
        }
        #pragma unroll
        for (int j = 0; j < NP; ++j) {
            a0[j] = ffma2(wi, v[j], a0[j]);
            a1[j] = ffma2(wf, v[j], a1[j]);
            a2[j] = ffma2(wg, v[j], a2[j]);
            a3[j] = ffma2(wo, v[j], a3[j]);
        }
    }
}

template<int NP, int PB>
__device__ __forceinline__ void store_h(u64* __restrict__ hrow, const u64* hn)
{
    if constexpr (NP == 4) {
        *(ulonglong2*)(hrow + PB)     = make_ulonglong2(hn[0], hn[1]);
        *(ulonglong2*)(hrow + PB + 2) = make_ulonglong2(hn[2], hn[3]);
    } else if constexpr (PB == 8) {
        *(ulonglong2*)(hrow + 8) = make_ulonglong2(hn[0], hn[1]);
        hrow[10] = hn[2];
    } else {
        hrow[11] = hn[0];
        *(ulonglong2*)(hrow + 12) = make_ulonglong2(hn[1], hn[2]);
    }
}

// Group-autonomous mainloop: only bar.sync(barid, 64) per step. Groups free-run
// vs each other so one group's MUFU epilogue overlaps another's FMA GEMM on the
// shared SMSP. NX = NP prefetch slots cover all 2*NP*28 group-local x elements
// (ceil(224/64)=4, ceil(168/64)=3).
template<int NP, int PB>
__device__ __forceinline__ void mainloop(
    const float4* __restrict__ sWih, const float4* __restrict__ sWhh,
    u64* __restrict__ shT, u64* __restrict__ sxT,
    int u, int barid, u64 bi, u64 bf, u64 bg, u64 bo,
    const float* const* xq, const bool* gg, const bool* vv, const int* sl)
{
    float cc[2 * NP];
    #pragma unroll
    for (int j = 0; j < 2 * NP; ++j) cc[j] = 0.0f;

    for (int t = 0; t < T_DIM; ++t) {
        const int cur = t & 1, nxt = cur ^ 1;
        // prefetch x(t+1) from gmem (hidden under GEMM)
        float xr[NP];
        if (t + 1 < T_DIM) {
            #pragma unroll
            for (int j = 0; j < NP; ++j)
                xr[j] = gg[j] ? xq[j][(t + 1) * I_DIM] : 0.0f;
        }

        u64 a0[NP], a1[NP], a2[NP], a3[NP];
        #pragma unroll
        for (int j = 0; j < NP; ++j) { a0[j] = bi; a1[j] = bf; a2[j] = bg; a3[j] = bo; }

        accum<I_DIM, NP, PB>(sWih, sxT + cur * (I_DIM * ST), u, a0, a1, a2, a3);
        accum<H_DIM, NP, PB>(sWhh, shT + cur * (H_DIM * ST), u, a0, a1, a2, a3);

        // epilogue
        u64 hn[NP];
        #pragma unroll
        for (int j = 0; j < NP; ++j) {
            float v0, v1;
            unpack2(a0[j], v0, v1); float i0 = sigm(v0),   i1 = sigm(v1);
            unpack2(a1[j], v0, v1); float f0 = sigm(v0),   f1 = sigm(v1);
            unpack2(a2[j], v0, v1); float g0_ = tanh_(v0), g1_ = tanh_(v1);
            unpack2(a3[j], v0, v1); float o0 = sigm(v0),   o1 = sigm(v1);
            float c0 = fmaf(f0, cc[2 * j],     i0 * g0_);
            float c1 = fmaf(f1, cc[2 * j + 1], i1 * g1_);
            cc[2 * j] = c0; cc[2 * j + 1] = c1;
            hn[j] = pack2(o0 * tanh_(c0), o1 * tanh_(c1));
        }
        store_h<NP, PB>(shT + nxt * (H_DIM * ST) + u * ST, hn);

        // stage x(t+1) into next buffer (group-local slots; ALL NP rounds)
        if (t + 1 < T_DIM) {
            float* xd = (float*)(sxT + nxt * (I_DIM * ST));
            #pragma unroll
            for (int j = 0; j < NP; ++j)
                if (vv[j]) xd[sl[j]] = xr[j];
        }
        bar_group(barid);   // 64-thread group barrier — the ONLY per-step sync
    }
}

__global__ void __launch_bounds__(THREADS, 1)
lstm_kernel(const float* __restrict__ x,
            const float* __restrict__ W_ih,
            const float* __restrict__ W_hh,
            const float* __restrict__ b_ih,
            const float* __restrict__ b_hh,
            const float* __restrict__ W_out,
            const float* __restrict__ b_out,
            float* __restrict__ out)
{
    extern __shared__ float smem_f[];
    float4* sWhh = (float4*)smem_f;
    float4* sWih = sWhh + H_DIM * H_DIM;
    float4* sb   = sWih + I_DIM * H_DIM;
    u64*    shT  = (u64*)(sb + H_DIM);        // 2 x [k][ST]
    u64*    sxT  = shT + 2 * H_DIM * ST;      // 2 x [i][ST]

    const int tid = threadIdx.x;
    const int u   = tid & 63;                 // hidden unit (lane within group)
    const int q   = tid >> 6;                 // pair-group, 2 warps each
    const int np  = (q < 2) ? 4 : 3;
    const int pb  = (q < 2) ? 4 * q : (q == 2 ? 8 : 11);
    const int row0 = blockIdx.x * ROWS;

    // ---- weight staging (gate-interleaved float4, [row][u]) ----
    for (int idx = tid; idx < I_DIM * H_DIM; idx += THREADS) {
        int uu = idx & 63, ii = idx >> 6;
        sWih[ii * H_DIM + uu] = make_float4(
            W_ih[uu * I_DIM + ii],
            W_ih[(64 + uu) * I_DIM + ii],
            W_ih[(128 + uu) * I_DIM + ii],
            W_ih[(192 + uu) * I_DIM + ii]);
    }
    for (int idx = tid; idx < H_DIM * H_DIM; idx += THREADS) {
        int uu = idx & 63, kk = idx >> 6;
        sWhh[kk * H_DIM + uu] = make_float4(
            W_hh[uu * H_DIM + kk],
            W_hh[(64 + uu) * H_DIM + kk],
            W_hh[(128 + uu) * H_DIM + kk],
            W_hh[(192 + uu) * H_DIM + kk]);
    }
    if (tid < H_DIM) {
        sb[tid] = make_float4(b_ih[tid] + b_hh[tid],
                              b_ih[64 + tid] + b_hh[64 + tid],
                              b_ih[128 + tid] + b_hh[128 + tid],
                              b_ih[192 + tid] + b_hh[192 + tid]);
    }
    for (int idx = tid; idx < H_DIM * ST; idx += THREADS) shT[idx] = 0ull;  // h(0)=0

    // ---- group-local x assignments: group q owns rows [2*pb, 2*pb+2*np) ----
    // nelems = 2*np*28 (224 or 168); 64 threads x np slots covers all (np>=ceil).
    const int nelems = 2 * np * I_DIM;
    int sl[4]; bool vv[4], gg[4]; const float* xq[4];
    #pragma unroll
    for (int j = 0; j < 4; ++j) {
        int e = u + j * 64;
        bool valid = (j < np) && (e < nelems);
        int ec = valid ? e : 0;
        int rl = ec / I_DIM, ii = ec - rl * I_DIM;
        int grow = row0 + 2 * pb + rl;
        vv[j] = valid;
        gg[j] = valid && (grow < B_DIM);
        xq[j] = x + (size_t)(gg[j] ? grow : 0) * TI + ii;
        sl[j] = ii * ST_F + 2 * pb + rl;
    }
    // stage x(0) into buffer 0
    {
        float* x0 = (float*)sxT;
        #pragma unroll
        for (int j = 0; j < 4; ++j)
            if (vv[j]) x0[sl[j]] = gg[j] ? xq[j][0] : 0.0f;
    }

    __syncthreads();   // weights + biases + h0 + x0 visible (full CTA, once)
    float4 bv = sb[u];
    u64 bi = pack2(bv.x, bv.x), bf = pack2(bv.y, bv.y);
    u64 bg = pack2(bv.z, bv.z), bo = pack2(bv.w, bv.w);

    switch (q) {
        case 0: mainloop<4, 0 >(sWih, sWhh, shT, sxT, u, 1, bi, bf, bg, bo, xq, gg, vv, sl); break;
        case 1: mainloop<4, 4 >(sWih, sWhh, shT, sxT, u, 2, bi, bf, bg, bo, xq, gg, vv, sl); break;
        case 2: mainloop<3, 8 >(sWih, sWhh, shT, sxT, u, 3, bi, bf, bg, bo, xq, gg, vv, sl); break;
        default: mainloop<3, 11>(sWih, sWhh, shT, sxT, u, 4, bi, bf, bg, bo, xq, gg, vv, sl); break;
    }

    __syncthreads();   // all groups' h(T) visible (full CTA, once)

    // ---- output head: T=128 even -> final h in buffer 0; h[k][r] at float k*ST_F + r ----
    const float* hf = (const float*)shT;
    for (int e = tid; e < ROWS * OUT_DIM; e += THREADS) {
        int r = e / OUT_DIM, o = e - r * OUT_DIM;
        if (row0 + r < B_DIM) {
            float a = b_out[o];
            #pragma unroll
            for (int k = 0; k < H_DIM; ++k)
                a = fmaf(hf[k * ST_F + r], W_out[o * H_DIM + k], a);
            out[(size_t)(row0 + r) * OUT_DIM + o] = a;
        }
    }
}

extern "C" void kernel_launch(void* const* d_in, const int* in_sizes, int n_in,
                              void* d_out, int out_size) {
    const float* x     = (const float*)d_in[0];
    const float* W_ih  = (const float*)d_in[1];
    const float* W_hh  = (const float*)d_in[2];
    const float* b_ih  = (const float*)d_in[3];
    const float* b_hh  = (const float*)d_in[4];
    const float* W_out = (const float*)d_in[5];
    const float* b_out = (const float*)d_in[6];
    float* out = (float*)d_out;

    cudaFuncSetAttribute(lstm_kernel, cudaFuncAttributeMaxDynamicSharedMemorySize, SMEM_BYTES);
    lstm_kernel<<<NBLOCKS, THREADS, SMEM_BYTES>>>(x, W_ih, W_hh, b_ih, b_hh, W_out, b_out, out);
}